// round 6
// baseline (speedup 1.0000x reference)
#include <cuda_runtime.h>
#include <cuda_bf16.h>

// Problem constants
#define PN   64
#define PTC  256
#define PK   32
#define PTK  64
#define PD   256
#define D4   (PD/4)          // 64 float4 per row
#define FULL_T (PTK + PTC)   // 320

#define NB_KNOW (PN * PK)                  // 2048
#define NB_POOL (NB_KNOW + PN)             // 2112
#define NB_GCTX ((PN * PTC) / 4)           // 4096 (4 ctx rows per block)
#define NB_MEGA (NB_POOL + NB_GCTX)        // 6208

// Scratch (device globals — no allocation allowed)
__device__ float g_ctx_use[PN * PD];
__device__ float g_know_use[PN * PK * PD];
__device__ int   g_cs[PN];

// ck_mask dtype probe: jax bool may arrive as 1-byte bool or int32.
__device__ __forceinline__ bool ck_mask_at(const unsigned char* p, int idx) {
    unsigned int w0 = *(const unsigned int*)p;
    if ((w0 & 0xFFFFFF00u) != 0u) {
        return p[idx] != 0;                          // int8 bool layout
    } else {
        return ((const int*)p)[idx] != 0;            // int32 layout
    }
}

// 8-wide batched accumulate: 8 independent LDG.128.CG in flight, then FMAs.
__device__ __forceinline__ void batch8(const float4* __restrict__ e4,
                                       const int* __restrict__ toks,
                                       int t0, int j,
                                       float4& acc, float& lenf)
{
    int tk[8];
    #pragma unroll
    for (int i = 0; i < 8; i++) tk[i] = toks[t0 + i];
    float4 v[8];
    #pragma unroll
    for (int i = 0; i < 8; i++) v[i] = __ldcg(&e4[(size_t)tk[i] * D4 + j]);
    #pragma unroll
    for (int i = 0; i < 8; i++) {
        float w = (tk[i] != 0) ? 1.0f : 0.0f;
        acc.x = fmaf(w, v[i].x, acc.x);
        acc.y = fmaf(w, v[i].y, acc.y);
        acc.z = fmaf(w, v[i].z, acc.z);
        acc.w = fmaf(w, v[i].w, acc.w);
        lenf += w;
    }
}

// ---------------------------------------------------------------------------
// Mega kernel: three block types in one grid so the dependency-free ctx part
// of the output gather overlaps the L2-bandwidth-bound pooling phase.
//   b in [0, 2048):        know pooling (n,k) — feeds attn
//   b in [2048, 2112):     ctx pooling (n)    — feeds attn
//   b in [2112, 6208):     gather_ctx — writes full_enc ctx rows + mask
// 256 threads, j = tid & 63 (float4 column), tq = tid >> 6.
// ---------------------------------------------------------------------------
__global__ __launch_bounds__(256, 4)
void mega_kernel(const int* __restrict__ src_tokens,
                 const int* __restrict__ know_tokens,
                 const unsigned char* __restrict__ ckm,
                 const float* __restrict__ embed,
                 float* __restrict__ out_enc,
                 float* __restrict__ out_mask)
{
    __shared__ int    toks[PTC];
    __shared__ float4 part[4][D4];     // 4 KB
    __shared__ float  lenp[4];

    const int tid = threadIdx.x;
    const int j   = tid & 63;
    const int tq  = tid >> 6;
    const int b   = blockIdx.x;
    const float4* __restrict__ e4 = (const float4*)embed;

    if (b >= NB_POOL) {
        // ---- gather_ctx: 4 output rows per block, branchless ----
        const int rc = (b - NB_POOL) * 4 + tq;      // 0 .. N*TC-1
        const int n  = rc >> 8;                      // / 256
        const int tc = rc & 255;
        const int tok = src_tokens[n * PTC + tc];
        const float w = (tok != 0) ? 1.0f : 0.0f;
        const int row = (tok != 0) ? tok : 0;
        float4 v = __ldcg(&e4[(size_t)row * D4 + j]);
        const size_t r = (size_t)n * FULL_T + PTK + tc;
        __stcs(&((float4*)out_enc)[r * D4 + j],
               make_float4(w * v.x, w * v.y, w * v.z, w * v.w));
        if (j == 0) out_mask[r] = w;
        return;
    }

    float4 acc = make_float4(0.f, 0.f, 0.f, 0.f);
    float  lenf = 0.f;
    float* dst;

    if (b < NB_KNOW) {
        const int n = b / PK;
        if (tid < PTK) toks[tid] = know_tokens[(size_t)b * PTK + tid];
        __syncthreads();
        const float cmv = ck_mask_at(ckm, n * PK + (b % PK)) ? 1.0f : 0.0f;

        const int t0 = tq * 16;
        batch8(e4, toks, t0,     j, acc, lenf);
        batch8(e4, toks, t0 + 8, j, acc, lenf);

        acc.x *= cmv; acc.y *= cmv; acc.z *= cmv; acc.w *= cmv;
        lenf *= cmv;
        dst = g_know_use + (size_t)b * PD;
    } else {
        const int n = b - NB_KNOW;
        toks[tid] = src_tokens[n * PTC + tid];
        __syncthreads();

        const int t0 = tq * 64;
        #pragma unroll
        for (int bt = 0; bt < 8; bt++)
            batch8(e4, toks, t0 + bt * 8, j, acc, lenf);

        dst = g_ctx_use + (size_t)n * PD;
    }

    part[tq][j] = acc;
    if (j == 0) lenp[tq] = lenf;
    __syncthreads();

    if (tq == 0) {
        float4 p0 = part[0][j], p1 = part[1][j], p2 = part[2][j], p3 = part[3][j];
        float4 a = make_float4(p0.x + p1.x + p2.x + p3.x,
                               p0.y + p1.y + p2.y + p3.y,
                               p0.z + p1.z + p2.z + p3.z,
                               p0.w + p1.w + p2.w + p3.w);
        float L = lenp[0] + lenp[1] + lenp[2] + lenp[3];
        float s = rsqrtf(256.0f * fmaxf(L, 1.0f));
        ((float4*)dst)[j] = make_float4(a.x * s, a.y * s, a.z * s, a.w * s);
    }
}

// ---------------------------------------------------------------------------
// Kernel 2: ck_attn = know_use . ctx_use, argmax selection, write ck_attn out.
// One block per n, 256 threads (8 warps, warp w handles k = w, w+8, ...).
// ---------------------------------------------------------------------------
__global__ __launch_bounds__(256)
void attn_kernel(const int* __restrict__ cs_ids,
                 const int* __restrict__ use_cs_ids,
                 const unsigned char* __restrict__ ckm,
                 float* __restrict__ out_ck_attn)
{
    const int n = blockIdx.x;
    const int wid = threadIdx.x >> 5;
    const int lane = threadIdx.x & 31;
    __shared__ float scores[PK];

    const float* __restrict__ cu = g_ctx_use + (size_t)n * PD;
    for (int k = wid; k < PK; k += 8) {
        const float* __restrict__ ku = g_know_use + ((size_t)n * PK + k) * PD;
        float p = 0.f;
        #pragma unroll
        for (int i = lane; i < PD; i += 32) p += ku[i] * cu[i];
        #pragma unroll
        for (int o = 16; o; o >>= 1) p += __shfl_xor_sync(0xFFFFFFFFu, p, o);
        if (lane == 0) scores[k] = p;
    }
    __syncthreads();

    if (threadIdx.x == 0) {
        int use = *use_cs_ids;
        int best = 0;
        float bv = -__int_as_float(0x7f800000);  // -inf
        #pragma unroll
        for (int k = 0; k < PK; k++) {
            float v = ck_mask_at(ckm, n * PK + k) ? scores[k] : -__int_as_float(0x7f800000);
            if (v > bv) { bv = v; best = k; }   // first-max (strict >) matches jnp.argmax
        }
        g_cs[n] = use ? cs_ids[n] : best;
    }
    if (threadIdx.x < PK) {
        bool cm = ck_mask_at(ckm, n * PK + threadIdx.x);
        out_ck_attn[n * PK + threadIdx.x] = cm ? scores[threadIdx.x] : 0.0f;
    }
}

// ---------------------------------------------------------------------------
// Kernel 3: gather the SELECTED knowledge rows only (needs g_cs).
// N*TK = 4096 rows, 4 rows per block -> 1024 blocks. Branchless.
// ---------------------------------------------------------------------------
__global__ __launch_bounds__(256)
void gather_know_kernel(const int* __restrict__ know_tokens,
                        const unsigned char* __restrict__ ckm,
                        const float* __restrict__ embed,
                        float* __restrict__ out_enc,
                        float* __restrict__ out_mask)
{
    const int tid = threadIdx.x;
    const int j   = tid & 63;
    const int rk  = blockIdx.x * 4 + (tid >> 6);   // 0 .. N*TK-1
    const int n = rk >> 6;                          // / 64
    const int t = rk & 63;

    const int cs = g_cs[n];
    const int tok = know_tokens[((size_t)n * PK + cs) * PTK + t];
    const bool m = (tok != 0) && ck_mask_at(ckm, n * PK + cs);

    const float w = m ? 1.0f : 0.0f;
    const int row = m ? tok : 0;
    float4 v = __ldcg(&((const float4*)embed)[(size_t)row * D4 + j]);
    const size_t r = (size_t)n * FULL_T + t;
    __stcs(&((float4*)out_enc)[r * D4 + j],
           make_float4(w * v.x, w * v.y, w * v.z, w * v.w));
    if (j == 0) out_mask[r] = w;
}

// ---------------------------------------------------------------------------
extern "C" void kernel_launch(void* const* d_in, const int* in_sizes, int n_in,
                              void* d_out, int out_size)
{
    const int*           src_tokens  = (const int*)d_in[0];            // [N,TC]
    const int*           know_tokens = (const int*)d_in[1];            // [N,K,TK]
    const unsigned char* ck_mask     = (const unsigned char*)d_in[2];  // [N,K] bool
    const int*           cs_ids      = (const int*)d_in[3];            // [N]
    const int*           use_cs_ids  = (const int*)d_in[4];            // scalar
    const float*         embed       = (const float*)d_in[5];          // [V,D]

    float* out = (float*)d_out;
    float* out_enc     = out;                                   // N*320*256
    float* out_mask    = out + (size_t)PN * FULL_T * PD;        // N*320
    float* out_ck_attn = out_mask + (size_t)PN * FULL_T;        // N*K

    mega_kernel<<<NB_MEGA, 256>>>(src_tokens, know_tokens, ck_mask, embed,
                                  out_enc, out_mask);
    attn_kernel<<<PN, 256>>>(cs_ids, use_cs_ids, ck_mask, out_ck_attn);
    gather_know_kernel<<<(PN * PTK) / 4, 256>>>(know_tokens, ck_mask, embed,
                                                out_enc, out_mask);
}